// round 7
// baseline (speedup 1.0000x reference)
#include <cuda_runtime.h>
#include <cuda_bf16.h>
#include <cstdint>

// ============================================================================
// Gps, bf16 3-term split mma.sync m16n8k16, ldmatrix + swizzle, 1 barrier/chunk.
//   agg0 = 0.5  * adj1 @ f1                       -> g_agg0 [16384,256]
//   aggm = .125 * fold4(adj2) @ f2                -> g_aggm [16384,256]
//   h    = lrelu([feat[seed] | agg0] @ W1^T)      -> g_h    (concat fused in fill)
//   out  = lrelu([h | aggm] @ W2^T)
// A: fp32 LDG -> bf16 hi/lo split in fill (reg double-buffered, 2 SMEM stages).
// B: pre-split bf16 hi/lo n-major [256,K], cp.async, 3 SMEM stages.
// G1+G2 merged into one 512-block launch to kill CTA-slot tail waste.
// ============================================================================

#define A_STAGE 16384            // Ah 8KB + Al 8KB
#define B_STAGE 16384            // Bh 8KB + Bl 8KB
#define OFF_B   32768            // A stages: 0,16384 ; B stages: 32768 + st*16384
#define SMEM_TOTAL (32768 + 3 * 16384)   // 81920

__device__ float g_agg0[16384 * 256];
__device__ float g_aggm[16384 * 256];
__device__ float g_h[16384 * 256];
__device__ __nv_bfloat16 g_f1b[2][256 * 4096];
__device__ __nv_bfloat16 g_f2b[2][256 * 2048];
__device__ __nv_bfloat16 g_W1b[2][256 * 512];
__device__ __nv_bfloat16 g_W2b[2][256 * 512];

__device__ __forceinline__ uint32_t smem_u32(const void* p) {
    uint32_t a;
    asm("{ .reg .u64 t; cvta.to.shared.u64 t, %1; cvt.u32.u64 %0, t; }" : "=r"(a) : "l"(p));
    return a;
}
__device__ __forceinline__ void cpa16(uint32_t dst, const void* src) {
    asm volatile("cp.async.cg.shared.global [%0], [%1], 16;" :: "r"(dst), "l"(src));
}
__device__ __forceinline__ uint32_t pk(__nv_bfloat16 a, __nv_bfloat16 b) {
    __nv_bfloat162 t; t.x = a; t.y = b;
    return *(uint32_t*)&t;
}
__device__ __forceinline__ void ldm4(uint32_t* r, uint32_t addr) {
    asm volatile("ldmatrix.sync.aligned.m8n8.x4.shared.b16 {%0,%1,%2,%3}, [%4];"
                 : "=r"(r[0]), "=r"(r[1]), "=r"(r[2]), "=r"(r[3]) : "r"(addr));
}
__device__ __forceinline__ void mma_bf16(float* c, const uint32_t* a, const uint32_t* b) {
    asm volatile(
        "mma.sync.aligned.m16n8k16.row.col.f32.bf16.bf16.f32 "
        "{%0,%1,%2,%3}, {%4,%5,%6,%7}, {%8,%9}, {%0,%1,%2,%3};"
        : "+f"(c[0]), "+f"(c[1]), "+f"(c[2]), "+f"(c[3])
        : "r"(a[0]), "r"(a[1]), "r"(a[2]), "r"(a[3]), "r"(b[0]), "r"(b[1]));
}
// 16B-granule XOR swizzle on 64B rows: conflict-free for ldmatrix octets.
__device__ __forceinline__ uint32_t swz16(int row, int g) {
    return row * 64 + ((g ^ ((row >> 1) & 3)) << 4);
}

struct GDesc {
    const float* A1; int lda1; int KA1;     // A cols [0,KA1): A1 (opt. gathered/folded)
    const int* seed; int fold;
    const float* A2; int lda2;              // A cols [KA1,K): A2
    const __nv_bfloat16* Bh; const __nv_bfloat16* Bl;  // [256,K] n-major
    float* C; int K; float scale; int lrelu;
};

__device__ __forceinline__ void gemm_body(const GDesc d, int bidx, char* smem) {
    const uint32_t sb = smem_u32(smem);
    const int tid = threadIdx.x;
    const int l = tid & 31, wid = tid >> 5;
    const int wm = wid & 1, wn = wid >> 1;          // 2m x 4n warps, warp 64x32
    const int bn = bidx & 1, bm = bidx >> 1;        // bn fastest -> L2 A reuse
    const int NK = d.K >> 5;

    float acc[4][4][4];
#pragma unroll
    for (int mt = 0; mt < 4; mt++)
#pragma unroll
        for (int nt = 0; nt < 4; nt++)
#pragma unroll
            for (int i = 0; i < 4; i++) acc[mt][nt][i] = 0.f;

    // hoist gather rows (4 fixed A-rows per thread)
    int srow[4];
#pragma unroll
    for (int j = 0; j < 4; j++) {
        const int m = bm * 128 + ((tid + j * 256) >> 3);
        srow[j] = d.seed ? d.seed[m] : (d.fold ? m * 4 : m);
    }

    auto ldgA = [&](int kc, float4* r) {
        const int k0 = kc << 5;
#pragma unroll
        for (int j = 0; j < 4; j++) {
            const int g = tid + j * 256;
            const int row = g >> 3, kg = k0 + ((g & 7) << 2);
            if (kg < d.KA1) {
                const float* p = d.A1 + (size_t)srow[j] * d.lda1 + kg;
                if (d.fold) {
                    float4 v0 = *(const float4*)p;
                    float4 v1 = *(const float4*)(p + d.lda1);
                    float4 v2 = *(const float4*)(p + 2 * d.lda1);
                    float4 v3 = *(const float4*)(p + 3 * d.lda1);
                    r[j].x = (v0.x + v1.x) + (v2.x + v3.x);
                    r[j].y = (v0.y + v1.y) + (v2.y + v3.y);
                    r[j].z = (v0.z + v1.z) + (v2.z + v3.z);
                    r[j].w = (v0.w + v1.w) + (v2.w + v3.w);
                } else {
                    r[j] = *(const float4*)p;
                }
            } else {
                r[j] = *(const float4*)(d.A2 + (size_t)(bm * 128 + row) * d.lda2 +
                                        (kg - d.KA1));
            }
        }
    };
    auto stsA = [&](const float4* r, int st) {
        char* base = smem + st * A_STAGE;
#pragma unroll
        for (int j = 0; j < 4; j++) {
            const int g = tid + j * 256;
            const int row = g >> 3, q = g & 7;
            const uint32_t off = row * 64 + ((((q >> 1) ^ ((row >> 1) & 3)) << 4) |
                                             ((q & 1) << 3));
            __nv_bfloat16 hx = __float2bfloat16(r[j].x);
            __nv_bfloat16 hy = __float2bfloat16(r[j].y);
            __nv_bfloat16 hz = __float2bfloat16(r[j].z);
            __nv_bfloat16 hw = __float2bfloat16(r[j].w);
            uint2 hi, lo;
            hi.x = pk(hx, hy); hi.y = pk(hz, hw);
            lo.x = pk(__float2bfloat16(r[j].x - __bfloat162float(hx)),
                      __float2bfloat16(r[j].y - __bfloat162float(hy)));
            lo.y = pk(__float2bfloat16(r[j].z - __bfloat162float(hz)),
                      __float2bfloat16(r[j].w - __bfloat162float(hw)));
            *(uint2*)(base + off) = hi;
            *(uint2*)(base + 8192 + off) = lo;
        }
    };
    auto fillB = [&](int kc, int st) {
        const uint32_t bb = sb + OFF_B + st * B_STAGE;
        const int k0 = kc << 5;
#pragma unroll
        for (int j = 0; j < 2; j++) {
            const int g = tid + j * 256;
            const int row = g >> 2, q = g & 3;
            const size_t src = (size_t)(bn * 128 + row) * d.K + k0 + q * 8;
            const uint32_t so = swz16(row, q);
            cpa16(bb + so, d.Bh + src);
            cpa16(bb + 8192 + so, d.Bl + src);
        }
        asm volatile("cp.async.commit_group;" ::: "memory");
    };

    // fragment base addresses (ks=0, stage 0); per-ks: XOR 32, per-stage: +offset
    uint32_t aA[4], aB[2];
#pragma unroll
    for (int mt = 0; mt < 4; mt++)
        aA[mt] = sb + swz16(wm * 64 + mt * 16 + (l & 15), (l >> 4) & 1);
#pragma unroll
    for (int p = 0; p < 2; p++)
        aB[p] = sb + OFF_B +
                swz16(wn * 32 + p * 16 + ((l >> 4) & 1) * 8 + (l & 7), (l >> 3) & 1);

    // prologue
    fillB(0, 0);
    fillB(1, 1);
    {
        float4 a0[4];
        ldgA(0, a0);
        stsA(a0, 0);
    }

    int stB = 0, stF = 2;
    for (int k = 0; k < NK; k++) {
        if (k < NK - 1) asm volatile("cp.async.wait_group 1;" ::: "memory");
        else            asm volatile("cp.async.wait_group 0;" ::: "memory");
        __syncthreads();   // B(k) + A(k) visible; stages (k-1) free everywhere

        float4 ar2[4];
        if (k + 1 < NK) ldgA(k + 1, ar2);       // LDG latency hidden by compute(k)
        if (k + 2 < NK) fillB(k + 2, stF);

        const uint32_t bA = stB * 0 + (k & 1) * A_STAGE;   // A stage
        const uint32_t bB = stB * B_STAGE;                 // B stage
#pragma unroll
        for (int ks = 0; ks < 2; ks++) {
            const uint32_t kx = ks << 5;
            uint32_t bh[2][4], bl[2][4];
#pragma unroll
            for (int p = 0; p < 2; p++) {
                ldm4(bh[p], (aB[p] + bB) ^ kx);
                ldm4(bl[p], ((aB[p] + 8192) + bB) ^ kx);
            }
#pragma unroll
            for (int mt = 0; mt < 4; mt++) {
                uint32_t ah[4], al[4];
                ldm4(ah, (aA[mt] + bA) ^ kx);
                ldm4(al, ((aA[mt] + 8192) + bA) ^ kx);
#pragma unroll
                for (int nt = 0; nt < 4; nt++) {
                    const uint32_t* bhf = &bh[nt >> 1][(nt & 1) * 2];
                    const uint32_t* blf = &bl[nt >> 1][(nt & 1) * 2];
                    mma_bf16(acc[mt][nt], ah, bhf);
                    mma_bf16(acc[mt][nt], al, bhf);
                    mma_bf16(acc[mt][nt], ah, blf);
                }
            }
        }
        if (k + 1 < NK) stsA(ar2, (k + 1) & 1);
        stB++; if (stB == 3) stB = 0;
        stF++; if (stF == 3) stF = 0;
    }

    // epilogue (ldc = 256 for all outputs)
#pragma unroll
    for (int mt = 0; mt < 4; mt++) {
        const int r0 = bm * 128 + wm * 64 + mt * 16 + (l >> 2);
#pragma unroll
        for (int nt = 0; nt < 4; nt++) {
            const int c0 = bn * 128 + wn * 32 + nt * 8 + 2 * (l & 3);
#pragma unroll
            for (int h = 0; h < 2; h++) {
                float2 v;
                v.x = acc[mt][nt][2 * h + 0] * d.scale;
                v.y = acc[mt][nt][2 * h + 1] * d.scale;
                if (d.lrelu) {
                    v.x = (v.x >= 0.f) ? v.x : 0.01f * v.x;
                    v.y = (v.y >= 0.f) ? v.y : 0.01f * v.y;
                }
                *(float2*)(d.C + (size_t)(r0 + h * 8) * 256 + c0) = v;
            }
        }
    }
}

__global__ void __launch_bounds__(256, 2)
gemm_dual(GDesc d0, GDesc d1, int nb0) {
    extern __shared__ char smem[];
    const int b = blockIdx.x;
    if (b < nb0) gemm_body(d0, b, smem);
    else         gemm_body(d1, b - nb0, smem);
}
__global__ void __launch_bounds__(256, 2)
gemm_one(GDesc d) {
    extern __shared__ char smem[];
    gemm_body(d, blockIdx.x, smem);
}

// [K,256] fp32 -> hi/lo [256,K] bf16 (transpose + residual split)
__global__ void tsplit_bf(const float* __restrict__ in, __nv_bfloat16* __restrict__ hi,
                          __nv_bfloat16* __restrict__ lo, int K) {
    __shared__ float t[32][33];
    const int k0 = blockIdx.x * 32, n0 = blockIdx.y * 32;
    const int tx = threadIdx.x, ty = threadIdx.y;
#pragma unroll
    for (int i = 0; i < 32; i += 8)
        t[ty + i][tx] = in[(size_t)(k0 + ty + i) * 256 + n0 + tx];
    __syncthreads();
#pragma unroll
    for (int i = 0; i < 32; i += 8) {
        const float v = t[tx][ty + i];
        const __nv_bfloat16 h = __float2bfloat16(v);
        const size_t o = (size_t)(n0 + ty + i) * K + k0 + tx;
        hi[o] = h;
        lo[o] = __float2bfloat16(v - __bfloat162float(h));
    }
}
// [256,K] fp32 -> hi/lo bf16 elementwise (W already n-major)
__global__ void wsplit_bf(const float* __restrict__ in, __nv_bfloat16* __restrict__ hi,
                          __nv_bfloat16* __restrict__ lo) {
    const int i = blockIdx.x * 256 + threadIdx.x;
    const float v = in[i];
    const __nv_bfloat16 h = __float2bfloat16(v);
    hi[i] = h;
    lo[i] = __float2bfloat16(v - __bfloat162float(h));
}

extern "C" void kernel_launch(void* const* d_in, const int* in_sizes, int n_in,
                              void* d_out, int out_size) {
    const float* feat = (const float*)d_in[0];   // [100000,256]
    const float* adj1 = (const float*)d_in[1];   // [16384,4096]
    const float* f1 = (const float*)d_in[2];     // [4096,256]
    const float* adj2 = (const float*)d_in[3];   // [65536,2048]
    const float* f2 = (const float*)d_in[4];     // [2048,256]
    const float* W1 = (const float*)d_in[5];     // [256,512]
    const float* W2 = (const float*)d_in[6];     // [256,512]
    const int* seed = (const int*)d_in[7];       // [16384]
    float* out = (float*)d_out;                  // [16384,256]

    float *agg0, *aggm, *h;
    __nv_bfloat16 *f1b, *f2b, *W1b, *W2b;
    cudaGetSymbolAddress((void**)&agg0, g_agg0);
    cudaGetSymbolAddress((void**)&aggm, g_aggm);
    cudaGetSymbolAddress((void**)&h, g_h);
    cudaGetSymbolAddress((void**)&f1b, g_f1b);
    cudaGetSymbolAddress((void**)&f2b, g_f2b);
    cudaGetSymbolAddress((void**)&W1b, g_W1b);
    cudaGetSymbolAddress((void**)&W2b, g_W2b);

    cudaFuncSetAttribute(gemm_dual, cudaFuncAttributeMaxDynamicSharedMemorySize, SMEM_TOTAL);
    cudaFuncSetAttribute(gemm_one, cudaFuncAttributeMaxDynamicSharedMemorySize, SMEM_TOTAL);

    tsplit_bf<<<dim3(128, 8), dim3(32, 8)>>>(f1, f1b, f1b + 256 * 4096, 4096);
    tsplit_bf<<<dim3(64, 8), dim3(32, 8)>>>(f2, f2b, f2b + 256 * 2048, 2048);
    wsplit_bf<<<512, 256>>>(W1, W1b, W1b + 256 * 512);
    wsplit_bf<<<512, 256>>>(W2, W2b, W2b + 256 * 512);

    GDesc dG1 = {adj1, 4096, 4096, nullptr, 0, nullptr, 0,
                 f1b, f1b + 256 * 4096, agg0, 4096, 0.5f, 0};
    GDesc dG2 = {adj2, 2048, 2048, nullptr, 1, nullptr, 0,
                 f2b, f2b + 256 * 2048, aggm, 2048, 0.125f, 0};
    GDesc dG3 = {feat, 256, 256, seed, 0, agg0, 256,
                 W1b, W1b + 256 * 512, h, 512, 1.0f, 1};
    GDesc dG4 = {h, 256, 256, nullptr, 0, aggm, 256,
                 W2b, W2b + 256 * 512, out, 512, 1.0f, 1};

    // G1 (heavy) blocks first, G2 tail-fills the CTA slots
    gemm_dual<<<512, 256, SMEM_TOTAL>>>(dG1, dG2, 256);
    // h = lrelu([feat[seed] | agg0] @ W1^T)   (gather + concat fused)
    gemm_one<<<256, 256, SMEM_TOTAL>>>(dG3);
    // out = lrelu([h | aggm] @ W2^T)
    gemm_one<<<256, 256, SMEM_TOTAL>>>(dG4);
}

// round 8
// speedup vs baseline: 1.1884x; 1.1884x over previous
#include <cuda_runtime.h>
#include <cuda_fp16.h>
#include <cstdint>

// ============================================================================
// Gps via mma.sync m16n8k16 fp16, 2-term split (tensor-pipe-bound: cut MMAs).
//   A: single fp16 RN term (rms err ~1.5e-4), converted in the tile fill.
//   B: exact fp16 hi/lo split (pre-split, n-major [256,K]).
//   acc += a*b_hi + a*b_lo            (2 MMAs/elem vs 3 for bf16 3-term)
//   agg0 = 0.5  * adj1 @ f1           [16384,256]
//   aggm = .125 * fold4(adj2) @ f2    [16384,256]   (4-row sum fused in fill)
//   h    = lrelu([feat[seed] | agg0] @ W1^T)        (gather+concat fused)
//   out  = lrelu([h | aggm] @ W2^T)
// CTA 128x128x32, 8 warps (2m x 4n), 2-stage pipeline, grid(bn=2, bm=128).
// ============================================================================

#define STAGE 30720              // A 10240 | Bh 10240 | Bl 10240
#define SMEM_TOTAL (2 * STAGE)   // 61440
#define OFF_BH 10240
#define OFF_BL 20480
#define LDW 20                   // row stride in 4B words (80B)

__device__ float g_agg0[16384 * 256];
__device__ float g_aggm[16384 * 256];
__device__ float g_h[16384 * 256];
__device__ __half g_f1h[2][256 * 4096];
__device__ __half g_f2h[2][256 * 2048];
__device__ __half g_W1h[2][256 * 512];
__device__ __half g_W2h[2][256 * 512];

__device__ __forceinline__ uint32_t smem_u32(const void* p) {
    uint32_t a;
    asm("{ .reg .u64 t; cvta.to.shared.u64 t, %1; cvt.u32.u64 %0, t; }" : "=r"(a) : "l"(p));
    return a;
}
__device__ __forceinline__ void cpa16(uint32_t dst, const void* src) {
    asm volatile("cp.async.cg.shared.global [%0], [%1], 16;" :: "r"(dst), "l"(src));
}
__device__ __forceinline__ uint32_t pk(__half a, __half b) {
    __half2 t; t.x = a; t.y = b;
    return *(uint32_t*)&t;
}
__device__ __forceinline__ void mma_f16(float* c, const uint32_t* a, const uint32_t* b) {
    asm volatile(
        "mma.sync.aligned.m16n8k16.row.col.f32.f16.f16.f32 "
        "{%0,%1,%2,%3}, {%4,%5,%6,%7}, {%8,%9}, {%0,%1,%2,%3};"
        : "+f"(c[0]), "+f"(c[1]), "+f"(c[2]), "+f"(c[3])
        : "r"(a[0]), "r"(a[1]), "r"(a[2]), "r"(a[3]), "r"(b[0]), "r"(b[1]));
}

struct GDesc {
    const float* A1; int lda1; int KA1;   // cols [0,KA1): from A1 (gather/fold opt.)
    const int* seed; int fold;
    const float* A2; int lda2;            // cols [KA1,K): from A2
    const __half* Bh; const __half* Bl;   // [256, K] n-major
    float* C; int K; float scale; int lrelu;
};

__device__ __forceinline__ void gemm_body(const GDesc d, char* smem) {
    const uint32_t sb = smem_u32(smem);
    const int tid = threadIdx.x;
    const int l = tid & 31, wid = tid >> 5;
    const int wm = wid & 1, wn = wid >> 1;           // 2m x 4n warps, warp 64x32
    const int bn = blockIdx.x, bm = blockIdx.y;      // bn fastest -> L2 A reuse
    const int NK = d.K >> 5;

    float acc[4][4][4];
#pragma unroll
    for (int mt = 0; mt < 4; mt++)
#pragma unroll
        for (int nt = 0; nt < 4; nt++)
#pragma unroll
            for (int i = 0; i < 4; i++) acc[mt][nt][i] = 0.f;

    // hoisted source rows for this thread's 4 A granule-rows
    int srow[4];
#pragma unroll
    for (int j = 0; j < 4; j++) {
        const int m = bm * 128 + ((tid + j * 256) >> 3);
        srow[j] = d.seed ? d.seed[m] : (d.fold ? m * 4 : m);
    }

    auto ldgA = [&](int kc, float4* r) {
        const int k0 = kc << 5;
#pragma unroll
        for (int j = 0; j < 4; j++) {
            const int g = tid + j * 256;             // 1024 float4 granules
            const int row = g >> 3, kg = k0 + ((g & 7) << 2);
            if (kg < d.KA1) {
                const float* p = d.A1 + (size_t)srow[j] * d.lda1 + kg;
                if (d.fold) {
                    float4 v0 = *(const float4*)p;
                    float4 v1 = *(const float4*)(p + d.lda1);
                    float4 v2 = *(const float4*)(p + 2 * d.lda1);
                    float4 v3 = *(const float4*)(p + 3 * d.lda1);
                    r[j].x = (v0.x + v1.x) + (v2.x + v3.x);
                    r[j].y = (v0.y + v1.y) + (v2.y + v3.y);
                    r[j].z = (v0.z + v1.z) + (v2.z + v3.z);
                    r[j].w = (v0.w + v1.w) + (v2.w + v3.w);
                } else {
                    r[j] = *(const float4*)p;
                }
            } else {
                r[j] = *(const float4*)(d.A2 + (size_t)(bm * 128 + row) * d.lda2 +
                                        (kg - d.KA1));
            }
        }
    };
    auto stsA = [&](const float4* r, int s) {
        char* base = smem + s * STAGE;
#pragma unroll
        for (int j = 0; j < 4; j++) {
            const int g = tid + j * 256;
            const int row = g >> 3, q = g & 7;
            uint2 h;
            h.x = pk(__float2half(r[j].x), __float2half(r[j].y));
            h.y = pk(__float2half(r[j].z), __float2half(r[j].w));
            *(uint2*)(base + row * 80 + q * 8) = h;
        }
    };
    auto fillB = [&](int kc, int s) {
        const int k0 = kc << 5;
#pragma unroll
        for (int j = 0; j < 2; j++) {
            const int g = tid + j * 256;             // 512 granules of 16B (8 half)
            const int row = g >> 2, q = g & 3;
            const size_t src = (size_t)(bn * 128 + row) * d.K + k0 + q * 8;
            const uint32_t so = row * 80 + q * 16;
            cpa16(sb + s * STAGE + OFF_BH + so, d.Bh + src);
            cpa16(sb + s * STAGE + OFF_BL + so, d.Bl + src);
        }
    };

    // prologue
    fillB(0, 0);
    asm volatile("cp.async.commit_group;" ::: "memory");
    {
        float4 a0[4];
        ldgA(0, a0);
        stsA(a0, 0);
    }

    for (int k = 0; k < NK; k++) {
        const int s = k & 1;
        __syncthreads();                             // stage s^1 free
        float4 ar2[4];
        if (k + 1 < NK) {
            fillB(k + 1, s ^ 1);
            asm volatile("cp.async.commit_group;" ::: "memory");
            ldgA(k + 1, ar2);                        // LDGs fly during compute(k)
            asm volatile("cp.async.wait_group 1;" ::: "memory");
        } else {
            asm volatile("cp.async.wait_group 0;" ::: "memory");
        }
        __syncthreads();                             // stage s visible

        const uint32_t* Ah = (const uint32_t*)(smem + s * STAGE);
        const uint32_t* Bh = (const uint32_t*)(smem + s * STAGE + OFF_BH);
        const uint32_t* Bl = (const uint32_t*)(smem + s * STAGE + OFF_BL);
#pragma unroll
        for (int ks = 0; ks < 2; ks++) {
            const int kw = ks * 8 + (l & 3);
            uint32_t a[4][4];
#pragma unroll
            for (int mt = 0; mt < 4; mt++) {
                const int r = wm * 64 + mt * 16 + (l >> 2);
                a[mt][0] = Ah[r * LDW + kw];
                a[mt][1] = Ah[(r + 8) * LDW + kw];
                a[mt][2] = Ah[r * LDW + kw + 4];
                a[mt][3] = Ah[(r + 8) * LDW + kw + 4];
            }
#pragma unroll
            for (int nt = 0; nt < 4; nt++) {
                const int n = wn * 32 + nt * 8 + (l >> 2);
                uint32_t bh[2], bl[2];
                bh[0] = Bh[n * LDW + kw];
                bh[1] = Bh[n * LDW + kw + 4];
                bl[0] = Bl[n * LDW + kw];
                bl[1] = Bl[n * LDW + kw + 4];
#pragma unroll
                for (int mt = 0; mt < 4; mt++) {
                    mma_f16(acc[mt][nt], a[mt], bh);
                    mma_f16(acc[mt][nt], a[mt], bl);
                }
            }
        }
        if (k + 1 < NK) stsA(ar2, s ^ 1);            // hidden under MMA tail
    }

    // epilogue (all outputs ldc = 256)
#pragma unroll
    for (int mt = 0; mt < 4; mt++) {
        const int r0 = bm * 128 + wm * 64 + mt * 16 + (l >> 2);
#pragma unroll
        for (int nt = 0; nt < 4; nt++) {
            const int c0 = bn * 128 + wn * 32 + nt * 8 + 2 * (l & 3);
#pragma unroll
            for (int h = 0; h < 2; h++) {
                float2 v;
                v.x = acc[mt][nt][2 * h + 0] * d.scale;
                v.y = acc[mt][nt][2 * h + 1] * d.scale;
                if (d.lrelu) {
                    v.x = (v.x >= 0.f) ? v.x : 0.01f * v.x;
                    v.y = (v.y >= 0.f) ? v.y : 0.01f * v.y;
                }
                *(float2*)(d.C + (size_t)(r0 + h * 8) * 256 + c0) = v;
            }
        }
    }
}

__global__ void __launch_bounds__(256, 2)
gemm_mma(GDesc d) {
    extern __shared__ char smem[];
    gemm_body(d, smem);
}

// [K,256] fp32 -> hi/lo [256,K] fp16 (transpose + exact-residual split)
__global__ void tsplit_h(const float* __restrict__ in, __half* __restrict__ hi,
                         __half* __restrict__ lo, int K) {
    __shared__ float t[32][33];
    const int k0 = blockIdx.x * 32, n0 = blockIdx.y * 32;
    const int tx = threadIdx.x, ty = threadIdx.y;
#pragma unroll
    for (int i = 0; i < 32; i += 8)
        t[ty + i][tx] = in[(size_t)(k0 + ty + i) * 256 + n0 + tx];
    __syncthreads();
#pragma unroll
    for (int i = 0; i < 32; i += 8) {
        const float v = t[tx][ty + i];
        const __half h = __float2half(v);
        const size_t o = (size_t)(n0 + ty + i) * K + k0 + tx;
        hi[o] = h;
        lo[o] = __float2half(v - __half2float(h));
    }
}
// [256,K] fp32 -> hi/lo fp16 elementwise (W already n-major)
__global__ void wsplit_h(const float* __restrict__ in, __half* __restrict__ hi,
                         __half* __restrict__ lo) {
    const int i = blockIdx.x * 256 + threadIdx.x;
    const float v = in[i];
    const __half h = __float2half(v);
    hi[i] = h;
    lo[i] = __float2half(v - __half2float(h));
}

extern "C" void kernel_launch(void* const* d_in, const int* in_sizes, int n_in,
                              void* d_out, int out_size) {
    const float* feat = (const float*)d_in[0];   // [100000,256]
    const float* adj1 = (const float*)d_in[1];   // [16384,4096]
    const float* f1 = (const float*)d_in[2];     // [4096,256]
    const float* adj2 = (const float*)d_in[3];   // [65536,2048]
    const float* f2 = (const float*)d_in[4];     // [2048,256]
    const float* W1 = (const float*)d_in[5];     // [256,512]
    const float* W2 = (const float*)d_in[6];     // [256,512]
    const int* seed = (const int*)d_in[7];       // [16384]
    float* out = (float*)d_out;                  // [16384,256]

    float *agg0, *aggm, *h;
    __half *f1h, *f2h, *W1h, *W2h;
    cudaGetSymbolAddress((void**)&agg0, g_agg0);
    cudaGetSymbolAddress((void**)&aggm, g_aggm);
    cudaGetSymbolAddress((void**)&h, g_h);
    cudaGetSymbolAddress((void**)&f1h, g_f1h);
    cudaGetSymbolAddress((void**)&f2h, g_f2h);
    cudaGetSymbolAddress((void**)&W1h, g_W1h);
    cudaGetSymbolAddress((void**)&W2h, g_W2h);

    cudaFuncSetAttribute(gemm_mma, cudaFuncAttributeMaxDynamicSharedMemorySize, SMEM_TOTAL);

    tsplit_h<<<dim3(128, 8), dim3(32, 8)>>>(f1, f1h, f1h + 256 * 4096, 4096);
    tsplit_h<<<dim3(64, 8), dim3(32, 8)>>>(f2, f2h, f2h + 256 * 2048, 2048);
    wsplit_h<<<512, 256>>>(W1, W1h, W1h + 256 * 512);
    wsplit_h<<<512, 256>>>(W2, W2h, W2h + 256 * 512);

    GDesc dG1 = {adj1, 4096, 4096, nullptr, 0, nullptr, 0,
                 f1h, f1h + 256 * 4096, agg0, 4096, 0.5f, 0};
    GDesc dG2 = {adj2, 2048, 2048, nullptr, 1, nullptr, 0,
                 f2h, f2h + 256 * 2048, aggm, 2048, 0.125f, 0};
    GDesc dG3 = {feat, 256, 256, seed, 0, agg0, 256,
                 W1h, W1h + 256 * 512, h, 512, 1.0f, 1};
    GDesc dG4 = {h, 256, 256, nullptr, 0, aggm, 256,
                 W2h, W2h + 256 * 512, out, 512, 1.0f, 1};

    dim3 grid(2, 128), blk(256);
    gemm_mma<<<grid, blk, SMEM_TOTAL>>>(dG1);   // agg0
    gemm_mma<<<grid, blk, SMEM_TOTAL>>>(dG2);   // aggm (fold4 fused)
    gemm_mma<<<grid, blk, SMEM_TOTAL>>>(dG3);   // h  (gather+concat fused)
    gemm_mma<<<grid, blk, SMEM_TOTAL>>>(dG4);   // out
}

// round 9
// speedup vs baseline: 1.5832x; 1.3322x over previous
#include <cuda_runtime.h>
#include <cuda_fp16.h>
#include <cstdint>

// ============================================================================
// Gps via mma.sync m16n8k16 fp16, SINGLE-term both operands (1 MMA per elem).
//   A: fp16 RN in the tile fill.  B: fp16 RN pre-converted, n-major [256,K].
//   Error model (validated R5/R6/R8): A+B RN fp16 across 4 GEMMs ~ 4.5e-4.
//   agg0 = 0.5  * adj1 @ f1           [16384,256]
//   aggm = .125 * fold4(adj2) @ f2    [16384,256]   (4-row sum fused in fill)
//   h    = lrelu([feat[seed] | agg0] @ W1^T)        (gather+concat fused)
//   out  = lrelu([h | aggm] @ W2^T)
// CTA 128x128x32, 8 warps (2m x 4n), 2-stage pipeline, grid(bn=2, bm=128)
// (bn fastest so bn-pairs are L2-co-resident: adj read from DRAM once).
// ============================================================================

#define STAGE 20480              // A 10240 | B 10240
#define SMEM_TOTAL (2 * STAGE)   // 40960
#define OFF_B 10240
#define LDW 20                   // row stride in 4B words (80B)

__device__ float g_agg0[16384 * 256];
__device__ float g_aggm[16384 * 256];
__device__ float g_h[16384 * 256];
__device__ __half g_f1h[256 * 4096];
__device__ __half g_f2h[256 * 2048];
__device__ __half g_W1h[256 * 512];
__device__ __half g_W2h[256 * 512];

__device__ __forceinline__ uint32_t smem_u32(const void* p) {
    uint32_t a;
    asm("{ .reg .u64 t; cvta.to.shared.u64 t, %1; cvt.u32.u64 %0, t; }" : "=r"(a) : "l"(p));
    return a;
}
__device__ __forceinline__ void cpa16(uint32_t dst, const void* src) {
    asm volatile("cp.async.cg.shared.global [%0], [%1], 16;" :: "r"(dst), "l"(src));
}
__device__ __forceinline__ uint32_t pk(__half a, __half b) {
    __half2 t; t.x = a; t.y = b;
    return *(uint32_t*)&t;
}
__device__ __forceinline__ void mma_f16(float* c, const uint32_t* a, const uint32_t* b) {
    asm volatile(
        "mma.sync.aligned.m16n8k16.row.col.f32.f16.f16.f32 "
        "{%0,%1,%2,%3}, {%4,%5,%6,%7}, {%8,%9}, {%0,%1,%2,%3};"
        : "+f"(c[0]), "+f"(c[1]), "+f"(c[2]), "+f"(c[3])
        : "r"(a[0]), "r"(a[1]), "r"(a[2]), "r"(a[3]), "r"(b[0]), "r"(b[1]));
}

struct GDesc {
    const float* A1; int lda1; int KA1;   // cols [0,KA1): from A1 (gather/fold opt.)
    const int* seed; int fold;
    const float* A2; int lda2;            // cols [KA1,K): from A2
    const __half* B;                      // [256, K] n-major fp16
    float* C; int K; float scale; int lrelu;
};

__device__ __forceinline__ void gemm_body(const GDesc d, char* smem) {
    const uint32_t sb = smem_u32(smem);
    const int tid = threadIdx.x;
    const int l = tid & 31, wid = tid >> 5;
    const int wm = wid & 1, wn = wid >> 1;           // 2m x 4n warps, warp 64x32
    const int bn = blockIdx.x, bm = blockIdx.y;      // bn fastest -> L2 A reuse
    const int NK = d.K >> 5;

    float acc[4][4][4];
#pragma unroll
    for (int mt = 0; mt < 4; mt++)
#pragma unroll
        for (int nt = 0; nt < 4; nt++)
#pragma unroll
            for (int i = 0; i < 4; i++) acc[mt][nt][i] = 0.f;

    // hoisted source rows for this thread's 4 A granule-rows
    int srow[4];
#pragma unroll
    for (int j = 0; j < 4; j++) {
        const int m = bm * 128 + ((tid + j * 256) >> 3);
        srow[j] = d.seed ? d.seed[m] : (d.fold ? m * 4 : m);
    }

    auto ldgA = [&](int kc, float4* r) {
        const int k0 = kc << 5;
#pragma unroll
        for (int j = 0; j < 4; j++) {
            const int g = tid + j * 256;             // 1024 float4 granules
            const int row = g >> 3, kg = k0 + ((g & 7) << 2);
            if (kg < d.KA1) {
                const float* p = d.A1 + (size_t)srow[j] * d.lda1 + kg;
                if (d.fold) {
                    float4 v0 = *(const float4*)p;
                    float4 v1 = *(const float4*)(p + d.lda1);
                    float4 v2 = *(const float4*)(p + 2 * d.lda1);
                    float4 v3 = *(const float4*)(p + 3 * d.lda1);
                    r[j].x = (v0.x + v1.x) + (v2.x + v3.x);
                    r[j].y = (v0.y + v1.y) + (v2.y + v3.y);
                    r[j].z = (v0.z + v1.z) + (v2.z + v3.z);
                    r[j].w = (v0.w + v1.w) + (v2.w + v3.w);
                } else {
                    r[j] = *(const float4*)p;
                }
            } else {
                r[j] = *(const float4*)(d.A2 + (size_t)(bm * 128 + row) * d.lda2 +
                                        (kg - d.KA1));
            }
        }
    };
    auto stsA = [&](const float4* r, int s) {
        char* base = smem + s * STAGE;
#pragma unroll
        for (int j = 0; j < 4; j++) {
            const int g = tid + j * 256;
            const int row = g >> 3, q = g & 7;
            uint2 h;
            h.x = pk(__float2half(r[j].x), __float2half(r[j].y));
            h.y = pk(__float2half(r[j].z), __float2half(r[j].w));
            *(uint2*)(base + row * 80 + q * 8) = h;
        }
    };
    auto fillB = [&](int kc, int s) {
        const int k0 = kc << 5;
#pragma unroll
        for (int j = 0; j < 2; j++) {
            const int g = tid + j * 256;             // 512 granules of 16B (8 half)
            const int row = g >> 2, q = g & 3;
            cpa16(sb + s * STAGE + OFF_B + row * 80 + q * 16,
                  d.B + (size_t)(bn * 128 + row) * d.K + k0 + q * 8);
        }
    };

    // prologue
    fillB(0, 0);
    asm volatile("cp.async.commit_group;" ::: "memory");
    {
        float4 a0[4];
        ldgA(0, a0);
        stsA(a0, 0);
    }

    for (int k = 0; k < NK; k++) {
        const int s = k & 1;
        __syncthreads();                             // stage s^1 free
        float4 ar2[4];
        if (k + 1 < NK) {
            fillB(k + 1, s ^ 1);
            asm volatile("cp.async.commit_group;" ::: "memory");
            ldgA(k + 1, ar2);                        // LDGs fly during compute(k)
            asm volatile("cp.async.wait_group 1;" ::: "memory");
        } else {
            asm volatile("cp.async.wait_group 0;" ::: "memory");
        }
        __syncthreads();                             // stage s visible

        const uint32_t* Ah = (const uint32_t*)(smem + s * STAGE);
        const uint32_t* Bh = (const uint32_t*)(smem + s * STAGE + OFF_B);
#pragma unroll
        for (int ks = 0; ks < 2; ks++) {
            const int kw = ks * 8 + (l & 3);
            uint32_t a[4][4];
#pragma unroll
            for (int mt = 0; mt < 4; mt++) {
                const int r = wm * 64 + mt * 16 + (l >> 2);
                a[mt][0] = Ah[r * LDW + kw];
                a[mt][1] = Ah[(r + 8) * LDW + kw];
                a[mt][2] = Ah[r * LDW + kw + 4];
                a[mt][3] = Ah[(r + 8) * LDW + kw + 4];
            }
#pragma unroll
            for (int nt = 0; nt < 4; nt++) {
                const int n = wn * 32 + nt * 8 + (l >> 2);
                uint32_t b[2];
                b[0] = Bh[n * LDW + kw];
                b[1] = Bh[n * LDW + kw + 4];
#pragma unroll
                for (int mt = 0; mt < 4; mt++) mma_f16(acc[mt][nt], a[mt], b);
            }
        }
        if (k + 1 < NK) stsA(ar2, s ^ 1);            // hidden under MMA tail
    }

    // epilogue (all outputs ldc = 256)
#pragma unroll
    for (int mt = 0; mt < 4; mt++) {
        const int r0 = bm * 128 + wm * 64 + mt * 16 + (l >> 2);
#pragma unroll
        for (int nt = 0; nt < 4; nt++) {
            const int c0 = bn * 128 + wn * 32 + nt * 8 + 2 * (l & 3);
#pragma unroll
            for (int h = 0; h < 2; h++) {
                float2 v;
                v.x = acc[mt][nt][2 * h + 0] * d.scale;
                v.y = acc[mt][nt][2 * h + 1] * d.scale;
                if (d.lrelu) {
                    v.x = (v.x >= 0.f) ? v.x : 0.01f * v.x;
                    v.y = (v.y >= 0.f) ? v.y : 0.01f * v.y;
                }
                *(float2*)(d.C + (size_t)(r0 + h * 8) * 256 + c0) = v;
            }
        }
    }
}

__global__ void __launch_bounds__(256, 2)
gemm_mma(GDesc d) {
    extern __shared__ char smem[];
    gemm_body(d, smem);
}

// [K,256] fp32 -> [256,K] fp16 (transpose + RN convert)
__global__ void tconv_h(const float* __restrict__ in, __half* __restrict__ o, int K) {
    __shared__ float t[32][33];
    const int k0 = blockIdx.x * 32, n0 = blockIdx.y * 32;
    const int tx = threadIdx.x, ty = threadIdx.y;
#pragma unroll
    for (int i = 0; i < 32; i += 8)
        t[ty + i][tx] = in[(size_t)(k0 + ty + i) * 256 + n0 + tx];
    __syncthreads();
#pragma unroll
    for (int i = 0; i < 32; i += 8)
        o[(size_t)(n0 + ty + i) * K + k0 + tx] = __float2half(t[tx][ty + i]);
}
// [256,K] fp32 -> fp16 elementwise (W already n-major)
__global__ void wconv_h(const float* __restrict__ in, __half* __restrict__ o) {
    const int i = blockIdx.x * 256 + threadIdx.x;
    o[i] = __float2half(in[i]);
}

extern "C" void kernel_launch(void* const* d_in, const int* in_sizes, int n_in,
                              void* d_out, int out_size) {
    const float* feat = (const float*)d_in[0];   // [100000,256]
    const float* adj1 = (const float*)d_in[1];   // [16384,4096]
    const float* f1 = (const float*)d_in[2];     // [4096,256]
    const float* adj2 = (const float*)d_in[3];   // [65536,2048]
    const float* f2 = (const float*)d_in[4];     // [2048,256]
    const float* W1 = (const float*)d_in[5];     // [256,512]
    const float* W2 = (const float*)d_in[6];     // [256,512]
    const int* seed = (const int*)d_in[7];       // [16384]
    float* out = (float*)d_out;                  // [16384,256]

    float *agg0, *aggm, *h;
    __half *f1h, *f2h, *W1h, *W2h;
    cudaGetSymbolAddress((void**)&agg0, g_agg0);
    cudaGetSymbolAddress((void**)&aggm, g_aggm);
    cudaGetSymbolAddress((void**)&h, g_h);
    cudaGetSymbolAddress((void**)&f1h, g_f1h);
    cudaGetSymbolAddress((void**)&f2h, g_f2h);
    cudaGetSymbolAddress((void**)&W1h, g_W1h);
    cudaGetSymbolAddress((void**)&W2h, g_W2h);

    cudaFuncSetAttribute(gemm_mma, cudaFuncAttributeMaxDynamicSharedMemorySize, SMEM_TOTAL);

    tconv_h<<<dim3(128, 8), dim3(32, 8)>>>(f1, f1h, 4096);
    tconv_h<<<dim3(64, 8), dim3(32, 8)>>>(f2, f2h, 2048);
    wconv_h<<<512, 256>>>(W1, W1h);
    wconv_h<<<512, 256>>>(W2, W2h);

    GDesc dG1 = {adj1, 4096, 4096, nullptr, 0, nullptr, 0, f1h, agg0, 4096, 0.5f, 0};
    GDesc dG2 = {adj2, 2048, 2048, nullptr, 1, nullptr, 0, f2h, aggm, 2048, 0.125f, 0};
    GDesc dG3 = {feat, 256, 256, seed, 0, agg0, 256, W1h, h, 512, 1.0f, 1};
    GDesc dG4 = {h, 256, 256, nullptr, 0, aggm, 256, W2h, out, 512, 1.0f, 1};

    dim3 grid(2, 128), blk(256);
    gemm_mma<<<grid, blk, SMEM_TOTAL>>>(dG1);   // agg0
    gemm_mma<<<grid, blk, SMEM_TOTAL>>>(dG2);   // aggm (fold4 fused)
    gemm_mma<<<grid, blk, SMEM_TOTAL>>>(dG3);   // h  (gather+concat fused)
    gemm_mma<<<grid, blk, SMEM_TOTAL>>>(dG4);   // out
}